// round 7
// baseline (speedup 1.0000x reference)
#include <cuda_runtime.h>
#include <math.h>
#include <stdint.h>

// Causal depthwise conv1d, K=24, T=3000.
// y[b,c,t] = sum_{k=0..23} w[c,k] * x[b,c,t-23+k]
// w[c,k] = beta*exp(log(max(alpha,1e-6))*k)*(1 - u^2/2 + u^4/24), u=theta*k
//
// R7: persistent channel-resident CTAs (grid = C = 1024, single wave),
//     weights computed once per CTA, double-buffered TMA over the 16 batch
//     rows. Compute core identical to R4/R6 (scalar FFMA, R=12,
//     conflict-free 48B-stride LDS.128).

#define KSZ 24
#define T_LEN 3000
#define R_OUT 12
#define NACT (T_LEN / R_OUT)   // 250 active compute threads
#define NTHREADS 256
#define PAD 24
#define ROW_BYTES (T_LEN * 4)  // 12000, 16B multiple

__device__ __forceinline__ void mbar_wait(uint32_t mba, uint32_t parity) {
    uint32_t done;
    asm volatile(
        "{\n\t"
        ".reg .pred p;\n\t"
        "mbarrier.try_wait.parity.acquire.cta.shared::cta.b64 p, [%1], %2;\n\t"
        "selp.b32 %0, 1, 0, p;\n\t"
        "}"
        : "=r"(done) : "r"(mba), "r"(parity) : "memory");
    if (!done) {
        asm volatile(
            "{\n\t"
            ".reg .pred P1;\n\t"
            "WAIT_LOOP_%=:\n\t"
            "mbarrier.try_wait.parity.acquire.cta.shared::cta.b64 P1, [%0], %1, 0x989680;\n\t"
            "@P1 bra.uni WAIT_DONE_%=;\n\t"
            "bra.uni WAIT_LOOP_%=;\n\t"
            "WAIT_DONE_%=:\n\t"
            "}"
            :: "r"(mba), "r"(parity) : "memory");
    }
}

__global__ __launch_bounds__(NTHREADS, 7)
void ssm4d_conv_kernel(const float* __restrict__ x,
                       const float* __restrict__ alpha,
                       const float* __restrict__ beta,
                       const float* __restrict__ theta,
                       float* __restrict__ y,
                       int C, int B)
{
    // Two buffers: S[j][0..23] = zeros, S[j][24+t] = x[row, t]
    // Identity: y[t] = sum_k w[k] * S[t + 1 + k]
    __shared__ __align__(16) float S[2][PAD + T_LEN];
    __shared__ __align__(16) float sw[KSZ];
    __shared__ __align__(8)  unsigned long long mbar[2];

    const int c   = blockIdx.x;
    const int tid = threadIdx.x;

    const uint32_t mb0 = (uint32_t)__cvta_generic_to_shared(&mbar[0]);
    const uint32_t mb1 = (uint32_t)__cvta_generic_to_shared(&mbar[1]);
    const uint32_t sd0 = (uint32_t)__cvta_generic_to_shared(&S[0][PAD]);
    const uint32_t sd1 = (uint32_t)__cvta_generic_to_shared(&S[1][PAD]);

    if (tid == 0) {
        asm volatile("mbarrier.init.shared.b64 [%0], 1;" :: "r"(mb0) : "memory");
        asm volatile("mbarrier.init.shared.b64 [%0], 1;" :: "r"(mb1) : "memory");
    }

    // pads (written once; TMA never touches [0..23])
    if (tid < PAD / 4) {
        reinterpret_cast<float4*>(S[0])[tid] = make_float4(0.f, 0.f, 0.f, 0.f);
        reinterpret_cast<float4*>(S[1])[tid] = make_float4(0.f, 0.f, 0.f, 0.f);
    }
    // per-channel weights: once per CTA
    if (tid < KSZ) {
        float a  = alpha[c];
        float la = logf(fmaxf(a, 1e-6f));
        float d  = expf(la * (float)tid);
        float u  = theta[c] * (float)tid;
        float u2 = u * u;
        float ph = 1.0f - 0.5f * u2 + (u2 * u2) * (1.0f / 24.0f);
        sw[tid] = beta[c] * d * ph;
    }
    __syncthreads();   // barriers init'd, pads + weights visible

    // prologue: TMA row 0 -> buf 0
    if (tid == 0) {
        asm volatile("mbarrier.arrive.expect_tx.shared.b64 _, [%0], %1;"
                     :: "r"(mb0), "r"((uint32_t)ROW_BYTES) : "memory");
        asm volatile(
            "cp.async.bulk.shared::cluster.global.mbarrier::complete_tx::bytes "
            "[%0], [%1], %2, [%3];"
            :: "r"(sd0), "l"(x + (long)c * T_LEN), "r"((uint32_t)ROW_BYTES),
               "r"(mb0)
            : "memory");
    }

    // weights to registers once (kept across rows; tid<NACT threads only)
    float w[KSZ];
    if (tid < NACT) {
#pragma unroll
        for (int j = 0; j < KSZ / 4; j++) {
            float4 wv = reinterpret_cast<const float4*>(sw)[j];
            w[4 * j + 0] = wv.x; w[4 * j + 1] = wv.y;
            w[4 * j + 2] = wv.z; w[4 * j + 3] = wv.w;
        }
    }

    for (int r = 0; r < B; r++) {
        const int cur = r & 1;
        const long rowbase = ((long)r * C + c) * (long)T_LEN;

        // data for row r ready?
        mbar_wait(cur ? mb1 : mb0, (uint32_t)((r >> 1) & 1));

        // all threads done with the OTHER buffer (previous iteration's compute)
        __syncthreads();

        // issue TMA for row r+1 into the other buffer
        if (tid == 0 && r + 1 < B) {
            const uint32_t mbn = cur ? mb0 : mb1;
            const uint32_t sdn = cur ? sd0 : sd1;
            asm volatile("mbarrier.arrive.expect_tx.shared.b64 _, [%0], %1;"
                         :: "r"(mbn), "r"((uint32_t)ROW_BYTES) : "memory");
            asm volatile(
                "cp.async.bulk.shared::cluster.global.mbarrier::complete_tx::bytes "
                "[%0], [%1], %2, [%3];"
                :: "r"(sdn), "l"(x + ((long)(r + 1) * C + c) * (long)T_LEN),
                   "r"((uint32_t)ROW_BYTES), "r"(mbn)
                : "memory");
        }

        if (tid < NACT) {
            const float* Sc = S[cur];

            // window: X[0..35] = Sc[12*tid .. 12*tid+35]
            // 9 LDS.128, lane stride 48B -> conflict-free.
            float X[R_OUT + KSZ];
            const float4* S4 = reinterpret_cast<const float4*>(&Sc[R_OUT * tid]);
#pragma unroll
            for (int j = 0; j < 9; j++) {
                float4 v = S4[j];
                X[4 * j + 0] = v.x; X[4 * j + 1] = v.y;
                X[4 * j + 2] = v.z; X[4 * j + 3] = v.w;
            }

            // y[12*tid + j] = sum_k w[k] * X[j + 1 + k]
            float acc[R_OUT];
#pragma unroll
            for (int j = 0; j < R_OUT; j++) acc[j] = 0.0f;
#pragma unroll
            for (int k = 0; k < KSZ; k++) {
                float wk = w[k];
#pragma unroll
                for (int j = 0; j < R_OUT; j++)
                    acc[j] = fmaf(wk, X[j + 1 + k], acc[j]);
            }

            float4* yo = reinterpret_cast<float4*>(y + rowbase + R_OUT * tid);
#pragma unroll
            for (int j = 0; j < 3; j++) {
                float4 o;
                o.x = acc[4 * j + 0]; o.y = acc[4 * j + 1];
                o.z = acc[4 * j + 2]; o.w = acc[4 * j + 3];
                yo[j] = o;
            }
        }
    }
}

extern "C" void kernel_launch(void* const* d_in, const int* in_sizes, int n_in,
                              void* d_out, int out_size)
{
    const float* x     = (const float*)d_in[0];
    const float* alpha = (const float*)d_in[1];
    const float* beta  = (const float*)d_in[2];
    const float* theta = (const float*)d_in[3];
    float* y = (float*)d_out;

    const int C = in_sizes[1];                 // 1024
    const int B = in_sizes[0] / (C * T_LEN);   // 16

    dim3 grid(C);
    ssm4d_conv_kernel<<<grid, NTHREADS>>>(x, alpha, beta, theta, y, C, B);
}

// round 8
// speedup vs baseline: 2.7338x; 2.7338x over previous
#include <cuda_runtime.h>
#include <math.h>
#include <stdint.h>

// Causal depthwise conv1d, K=24, T=3000.
// y[b,c,t] = sum_{k=0..23} w[c,k] * x[b,c,t-23+k]
// w[c,k] = beta*exp(log(max(alpha,1e-6))*k)*(1 - u^2/2 + u^4/24), u=theta*k
//
// R8: R6 (TMA bulk fill, scalar-FFMA R=12 core, 7 CTAs/SM) with
//     register-pressure fix: weights are NOT preloaded into 24 registers;
//     each 4-tap group's weights come from one broadcast LDS.128 inside the
//     k-loop. Eliminates the spill seen at the 36-reg cap. int32 indexing.

#define KSZ 24
#define T_LEN 3000
#define R_OUT 12
#define NACT (T_LEN / R_OUT)   // 250 active compute threads
#define NTHREADS 256
#define PAD 24
#define ROW_BYTES (T_LEN * 4)  // 12000, 16B multiple

__global__ __launch_bounds__(NTHREADS, 7)
void ssm4d_conv_kernel(const float* __restrict__ x,
                       const float* __restrict__ alpha,
                       const float* __restrict__ beta,
                       const float* __restrict__ theta,
                       float* __restrict__ y,
                       int C)
{
    // S[0..23]  = zeros; S[24+t] = x[row,t];  y[t] = sum_k w[k]*S[t+1+k]
    __shared__ __align__(16) float S[PAD + T_LEN];
    __shared__ __align__(16) float sw[KSZ];
    __shared__ __align__(8)  unsigned long long mbar;

    const int c   = blockIdx.x;
    const int b   = blockIdx.y;
    const int tid = threadIdx.x;
    const int rowbase = (b * C + c) * T_LEN;   // < 2^31, int is safe

    const uint32_t mba  = (uint32_t)__cvta_generic_to_shared(&mbar);
    const uint32_t sdst = (uint32_t)__cvta_generic_to_shared(S + PAD);

    if (tid == 0)
        asm volatile("mbarrier.init.shared.b64 [%0], 1;" :: "r"(mba) : "memory");
    __syncthreads();

    if (tid == 0) {
        asm volatile("mbarrier.arrive.expect_tx.shared.b64 _, [%0], %1;"
                     :: "r"(mba), "r"((uint32_t)ROW_BYTES) : "memory");
        asm volatile(
            "cp.async.bulk.shared::cluster.global.mbarrier::complete_tx::bytes "
            "[%0], [%1], %2, [%3];"
            :: "r"(sdst), "l"(x + rowbase), "r"((uint32_t)ROW_BYTES), "r"(mba)
            : "memory");
    }

    // overlap with the TMA flight: zero pad + per-channel weights
    if (tid < PAD / 4)
        reinterpret_cast<float4*>(S)[tid] = make_float4(0.f, 0.f, 0.f, 0.f);
    if (tid < KSZ) {
        float a  = alpha[c];
        float la = logf(fmaxf(a, 1e-6f));
        float d  = expf(la * (float)tid);
        float u  = theta[c] * (float)tid;
        float u2 = u * u;
        float ph = 1.0f - 0.5f * u2 + (u2 * u2) * (1.0f / 24.0f);
        sw[tid] = beta[c] * d * ph;
    }
    __syncthreads();   // pad + weights visible to all

    // wait for TMA completion (phase 0), acquire for subsequent LDS
    {
        uint32_t done;
        asm volatile(
            "{\n\t"
            ".reg .pred p;\n\t"
            "mbarrier.try_wait.parity.acquire.cta.shared::cta.b64 p, [%1], %2;\n\t"
            "selp.b32 %0, 1, 0, p;\n\t"
            "}"
            : "=r"(done) : "r"(mba), "r"(0u) : "memory");
        if (!done) {
            asm volatile(
                "{\n\t"
                ".reg .pred P1;\n\t"
                "WAIT_LOOP:\n\t"
                "mbarrier.try_wait.parity.acquire.cta.shared::cta.b64 P1, [%0], %1, 0x989680;\n\t"
                "@P1 bra.uni WAIT_DONE;\n\t"
                "bra.uni WAIT_LOOP;\n\t"
                "WAIT_DONE:\n\t"
                "}"
                :: "r"(mba), "r"(0u) : "memory");
        }
    }

    if (tid < NACT) {
        // window: X[0..35] = S[12*tid .. 12*tid+35]
        // 9 LDS.128, lane stride 48B -> all 32 banks once per 8-lane phase:
        // conflict-free.
        float X[R_OUT + KSZ];   // 36
        const float4* S4 = reinterpret_cast<const float4*>(&S[R_OUT * tid]);
#pragma unroll
        for (int j = 0; j < 9; j++) {
            float4 v = S4[j];
            X[4 * j + 0] = v.x; X[4 * j + 1] = v.y;
            X[4 * j + 2] = v.z; X[4 * j + 3] = v.w;
        }

        // y[12*tid + j] = sum_k w[k] * X[j + 1 + k]
        // Weights fetched per 4-tap group from smem (broadcast LDS.128):
        // keeps live registers ~24-28, no spill at the 36-reg cap.
        float acc[R_OUT];
#pragma unroll
        for (int j = 0; j < R_OUT; j++) acc[j] = 0.0f;

        const float4* sw4 = reinterpret_cast<const float4*>(sw);
#pragma unroll
        for (int g = 0; g < KSZ / 4; g++) {
            float4 wv = sw4[g];
            const int k0 = 4 * g;
#pragma unroll
            for (int j = 0; j < R_OUT; j++)
                acc[j] = fmaf(wv.x, X[j + 1 + k0 + 0], acc[j]);
#pragma unroll
            for (int j = 0; j < R_OUT; j++)
                acc[j] = fmaf(wv.y, X[j + 1 + k0 + 1], acc[j]);
#pragma unroll
            for (int j = 0; j < R_OUT; j++)
                acc[j] = fmaf(wv.z, X[j + 1 + k0 + 2], acc[j]);
#pragma unroll
            for (int j = 0; j < R_OUT; j++)
                acc[j] = fmaf(wv.w, X[j + 1 + k0 + 3], acc[j]);
        }

        // 12 outputs: 3 aligned STG.128
        float4* yo = reinterpret_cast<float4*>(y + rowbase + R_OUT * tid);
#pragma unroll
        for (int j = 0; j < 3; j++) {
            float4 o;
            o.x = acc[4 * j + 0]; o.y = acc[4 * j + 1];
            o.z = acc[4 * j + 2]; o.w = acc[4 * j + 3];
            yo[j] = o;
        }
    }
}

extern "C" void kernel_launch(void* const* d_in, const int* in_sizes, int n_in,
                              void* d_out, int out_size)
{
    const float* x     = (const float*)d_in[0];
    const float* alpha = (const float*)d_in[1];
    const float* beta  = (const float*)d_in[2];
    const float* theta = (const float*)d_in[3];
    float* y = (float*)d_out;

    const int C = in_sizes[1];                 // 1024
    const int B = in_sizes[0] / (C * T_LEN);   // 16

    dim3 grid(C, B);
    ssm4d_conv_kernel<<<grid, NTHREADS>>>(x, alpha, beta, theta, y, C);
}

// round 9
// speedup vs baseline: 2.9424x; 1.0763x over previous
#include <cuda_runtime.h>
#include <math.h>
#include <stdint.h>

// Causal depthwise conv1d, K=24, T=3000.
// y[b,c,t] = sum_{k=0..23} w[c,k] * x[b,c,t-23+k]
// w[c,k] = beta*exp(log(max(alpha,1e-6))*k)*(1 - u^2/2 + u^4/24), u=theta*k
//
// R9: R8 core (TMA fill, scalar-FFMA R=12, in-loop broadcast weight LDS)
//     + TWO rows per CTA (same channel, batches b and b+B/2), both TMAs
//       issued upfront (prefetch depth 2, no lockstep loop), prologue and
//       weight MUFU amortized 2x, wave count halved
//     + 8 CTAs/SM (2048 thr, 32 regs = full RF, smem 8x24.4KB < 228KB).

#define KSZ 24
#define T_LEN 3000
#define R_OUT 12
#define NACT (T_LEN / R_OUT)   // 250 active compute threads
#define NTHREADS 256
#define PAD 24
#define ROW_BYTES (T_LEN * 4)  // 12000, 16B multiple

__device__ __forceinline__ void mbar_wait(uint32_t mba, uint32_t parity) {
    uint32_t done;
    asm volatile(
        "{\n\t"
        ".reg .pred p;\n\t"
        "mbarrier.try_wait.parity.acquire.cta.shared::cta.b64 p, [%1], %2;\n\t"
        "selp.b32 %0, 1, 0, p;\n\t"
        "}"
        : "=r"(done) : "r"(mba), "r"(parity) : "memory");
    if (!done) {
        asm volatile(
            "{\n\t"
            ".reg .pred P1;\n\t"
            "WAIT_LOOP_%=:\n\t"
            "mbarrier.try_wait.parity.acquire.cta.shared::cta.b64 P1, [%0], %1, 0x989680;\n\t"
            "@P1 bra.uni WAIT_DONE_%=;\n\t"
            "bra.uni WAIT_LOOP_%=;\n\t"
            "WAIT_DONE_%=:\n\t"
            "}"
            :: "r"(mba), "r"(parity) : "memory");
    }
}

__device__ __forceinline__ void tma_row(uint32_t sdst, const float* src,
                                        uint32_t mba) {
    asm volatile("mbarrier.arrive.expect_tx.shared.b64 _, [%0], %1;"
                 :: "r"(mba), "r"((uint32_t)ROW_BYTES) : "memory");
    asm volatile(
        "cp.async.bulk.shared::cluster.global.mbarrier::complete_tx::bytes "
        "[%0], [%1], %2, [%3];"
        :: "r"(sdst), "l"(src), "r"((uint32_t)ROW_BYTES), "r"(mba)
        : "memory");
}

__device__ __forceinline__ void compute_row(const float* __restrict__ Sc,
                                            const float* __restrict__ sw,
                                            float* __restrict__ y,
                                            int rowbase, int tid) {
    // window: X[0..35] = Sc[12*tid .. 12*tid+35]
    // 9 LDS.128, lane stride 48B -> all 32 banks once per 8-lane phase.
    float X[R_OUT + KSZ];
    const float4* S4 = reinterpret_cast<const float4*>(&Sc[R_OUT * tid]);
#pragma unroll
    for (int j = 0; j < 9; j++) {
        float4 v = S4[j];
        X[4 * j + 0] = v.x; X[4 * j + 1] = v.y;
        X[4 * j + 2] = v.z; X[4 * j + 3] = v.w;
    }

    float acc[R_OUT];
#pragma unroll
    for (int j = 0; j < R_OUT; j++) acc[j] = 0.0f;

    const float4* sw4 = reinterpret_cast<const float4*>(sw);
#pragma unroll
    for (int g = 0; g < KSZ / 4; g++) {
        float4 wv = sw4[g];
        const int k0 = 4 * g;
#pragma unroll
        for (int j = 0; j < R_OUT; j++)
            acc[j] = fmaf(wv.x, X[j + 1 + k0 + 0], acc[j]);
#pragma unroll
        for (int j = 0; j < R_OUT; j++)
            acc[j] = fmaf(wv.y, X[j + 1 + k0 + 1], acc[j]);
#pragma unroll
        for (int j = 0; j < R_OUT; j++)
            acc[j] = fmaf(wv.z, X[j + 1 + k0 + 2], acc[j]);
#pragma unroll
        for (int j = 0; j < R_OUT; j++)
            acc[j] = fmaf(wv.w, X[j + 1 + k0 + 3], acc[j]);
    }

    float4* yo = reinterpret_cast<float4*>(y + rowbase + R_OUT * tid);
#pragma unroll
    for (int j = 0; j < 3; j++) {
        float4 o;
        o.x = acc[4 * j + 0]; o.y = acc[4 * j + 1];
        o.z = acc[4 * j + 2]; o.w = acc[4 * j + 3];
        yo[j] = o;
    }
}

__global__ __launch_bounds__(NTHREADS, 8)
void ssm4d_conv_kernel(const float* __restrict__ x,
                       const float* __restrict__ alpha,
                       const float* __restrict__ beta,
                       const float* __restrict__ theta,
                       float* __restrict__ y,
                       int C, int Bh)
{
    // Two buffers: S[i][0..23] = zeros, S[i][24+t] = x[row_i, t]
    // Identity: y[t] = sum_k w[k] * S[t + 1 + k]
    __shared__ __align__(16) float S[2][PAD + T_LEN];
    __shared__ __align__(16) float sw[KSZ];
    __shared__ __align__(8)  unsigned long long mbar[2];

    const int c   = blockIdx.x;
    const int b0  = blockIdx.y;        // row pair: batches b0 and b0+Bh
    const int tid = threadIdx.x;
    const int row0 = (b0 * C + c) * T_LEN;
    const int row1 = ((b0 + Bh) * C + c) * T_LEN;

    const uint32_t mb0 = (uint32_t)__cvta_generic_to_shared(&mbar[0]);
    const uint32_t mb1 = (uint32_t)__cvta_generic_to_shared(&mbar[1]);
    const uint32_t sd0 = (uint32_t)__cvta_generic_to_shared(&S[0][PAD]);
    const uint32_t sd1 = (uint32_t)__cvta_generic_to_shared(&S[1][PAD]);

    if (tid == 0) {
        asm volatile("mbarrier.init.shared.b64 [%0], 1;" :: "r"(mb0) : "memory");
        asm volatile("mbarrier.init.shared.b64 [%0], 1;" :: "r"(mb1) : "memory");
    }
    __syncthreads();

    // both TMAs upfront: prefetch depth 2
    if (tid == 0) {
        tma_row(sd0, x + row0, mb0);
        tma_row(sd1, x + row1, mb1);
    }

    // overlap with TMA flight: pads + per-channel weights (once per 2 rows)
    if (tid < PAD / 4) {
        reinterpret_cast<float4*>(S[0])[tid] = make_float4(0.f, 0.f, 0.f, 0.f);
        reinterpret_cast<float4*>(S[1])[tid] = make_float4(0.f, 0.f, 0.f, 0.f);
    }
    if (tid < KSZ) {
        float a  = alpha[c];
        float la = logf(fmaxf(a, 1e-6f));
        float d  = expf(la * (float)tid);
        float u  = theta[c] * (float)tid;
        float u2 = u * u;
        float ph = 1.0f - 0.5f * u2 + (u2 * u2) * (1.0f / 24.0f);
        sw[tid] = beta[c] * d * ph;
    }
    __syncthreads();   // pads + weights visible

    mbar_wait(mb0, 0u);
    if (tid < NACT) compute_row(S[0], sw, y, row0, tid);

    mbar_wait(mb1, 0u);
    if (tid < NACT) compute_row(S[1], sw, y, row1, tid);
}

extern "C" void kernel_launch(void* const* d_in, const int* in_sizes, int n_in,
                              void* d_out, int out_size)
{
    const float* x     = (const float*)d_in[0];
    const float* alpha = (const float*)d_in[1];
    const float* beta  = (const float*)d_in[2];
    const float* theta = (const float*)d_in[3];
    float* y = (float*)d_out;

    const int C = in_sizes[1];                 // 1024
    const int B = in_sizes[0] / (C * T_LEN);   // 16

    dim3 grid(C, B / 2);
    ssm4d_conv_kernel<<<grid, NTHREADS>>>(x, alpha, beta, theta, y, C, B / 2);
}